// round 10
// baseline (speedup 1.0000x reference)
#include <cuda_runtime.h>
#include <math.h>
#include <stdint.h>

#define Bz   128
#define Sz   30
#define Hs   768
#define Is   3072
#define NHh  12
#define HDd  64
#define TOK  (Bz*Sz)     // 3840
#define Ee   15
#define Dd   14
#define Rr   29
#define LRr  8
#define LORA_SCAL 2.0f
#define QKVN 2304

// ---------------- scratch (static __device__, no allocations) ----------------
__device__ float d_h    [TOK*Hs];
__device__ float d_nx   [TOK*Hs];
__device__ float d_qkvb [TOK*QKVN];   // packed q|k|v activations
__device__ float d_attc [TOK*Hs];    // attention context (pre O-proj)
__device__ float d_att  [TOK*Hs];    // post O-proj (needed by classifier)
__device__ float d_res1 [TOK*Hs];
__device__ float d_nres [TOK*Hs];
__device__ float d_hid  [TOK*Is];    // base_hidden (post-gelu FFN up)
__device__ float d_bout [TOK*Hs];    // base_out
__device__ float d_t1   [TOK*(Ee*LRr)];
__device__ float d_g    [TOK*(Ee*LRr)];
__device__ float d_pooled[Dd*Bz*Hs];
__device__ float d_coef [TOK*Ee];
__device__ float d_M    [Ee*LRr*LRr];
__device__ float d_maskf[Rr*Dd];
__device__ float d_cnt  [Dd];
__device__ float d_actd [Bz*Dd];
__device__ float d_wqkv [12*QKVN*Hs];  // packed QKV weights
__device__ float d_bqkv [12*QKVN];

// ---------------- helpers ----------------
__device__ __forceinline__ float gelu_exact(float x){
    return 0.5f * x * (1.f + erff(x * 0.70710678118654752f));
}
__device__ __forceinline__ unsigned f2tf32(float x){
    unsigned u;
    asm("cvt.rna.tf32.f32 %0, %1;" : "=r"(u) : "f"(x));
    return u;
}
__device__ __forceinline__ void mma_tf32(float* c, const unsigned* a, const unsigned* b){
    asm volatile(
        "mma.sync.aligned.m16n8k8.row.col.f32.tf32.tf32.f32 "
        "{%0,%1,%2,%3}, {%4,%5,%6,%7}, {%8,%9}, {%0,%1,%2,%3};"
        : "+f"(c[0]), "+f"(c[1]), "+f"(c[2]), "+f"(c[3])
        : "r"(a[0]), "r"(a[1]), "r"(a[2]), "r"(a[3]), "r"(b[0]), "r"(b[1]));
}

// ---------------- build initial h = [cls ; region_features] ----------------
__global__ void k_build(const float* __restrict__ region, const float* __restrict__ cls,
                        float* __restrict__ h){
    int i = blockIdx.x*256 + threadIdx.x;
    if (i >= TOK*Hs) return;
    int t = i / Hs, hh = i % Hs;
    int b = t / Sz, s = t % Sz;
    h[i] = (s == 0) ? cls[hh] : region[((size_t)b*Rr + (s-1))*Hs + hh];
}

// ---------------- QKV weight/bias packing ----------------
__global__ void k_packqkv(const float* __restrict__ wq, const float* __restrict__ wk,
                          const float* __restrict__ wv, float* __restrict__ wqkv){
    long long i = (long long)blockIdx.x*256 + threadIdx.x;
    if (i >= (long long)12*QKVN*Hs) return;
    int l = (int)(i / (QKVN*Hs));
    int rem = (int)(i % (QKVN*Hs));
    int n = rem / Hs, k = rem % Hs;
    float v;
    if (n < 768)       v = wq[((size_t)l*768 + n      )*768 + k];
    else if (n < 1536) v = wk[((size_t)l*768 + n - 768)*768 + k];
    else               v = wv[((size_t)l*768 + n -1536)*768 + k];
    wqkv[i] = v;
}
__global__ void k_packb(const float* __restrict__ bq, const float* __restrict__ bk,
                        const float* __restrict__ bv, float* __restrict__ bqkv){
    int i = blockIdx.x*256 + threadIdx.x;
    if (i >= 12*QKVN) return;
    int l = i / QKVN, n = i % QKVN;
    float v;
    if (n < 768)       v = bq[l*768 + n];
    else if (n < 1536) v = bk[l*768 + n - 768];
    else               v = bv[l*768 + n - 1536];
    bqkv[i] = v;
}

// ---------------- layernorm over H=768 (256 thr, 3 elems/thread) ----------------
__global__ void k_ln(const float* __restrict__ x, float* __restrict__ y,
                     const float* __restrict__ g, const float* __restrict__ b, float eps){
    int t = blockIdx.x, tid = threadIdx.x;
    const float* xr = x + (size_t)t*Hs;
    float v0 = xr[tid], v1 = xr[tid+256], v2 = xr[tid+512];
    __shared__ float red[256], red2[256], mi[2];
    red[tid]  = v0+v1+v2;
    red2[tid] = v0*v0+v1*v1+v2*v2;
    __syncthreads();
    for (int st = 128; st > 0; st >>= 1){
        if (tid < st){ red[tid]+=red[tid+st]; red2[tid]+=red2[tid+st]; }
        __syncthreads();
    }
    if (tid == 0){
        float m = red[0]/768.f;
        float var = red2[0]/768.f - m*m;
        mi[0] = m; mi[1] = rsqrtf(var + eps);
    }
    __syncthreads();
    float m = mi[0], inv = mi[1];
    float* yr = y + (size_t)t*Hs;
    yr[tid]     = (v0-m)*inv*g[tid]     + b[tid];
    yr[tid+256] = (v1-m)*inv*g[tid+256] + b[tid+256];
    yr[tid+512] = (v2-m)*inv*g[tid+512] + b[tid+512];
}

// ---------------- 3xTF32 tensor-core GEMM, fragment-ordered smem ----------------
// C[M,N] = A[M,K] @ W[N,K]^T + bias (+gelu) ; optional C2 = C + res
// Block tile 128x64, BK=16, 256 threads (8 warps 4x2), warp tile 32x32.
// Smem stores tiles in exact MMA fragment order:
//  A chunk (mtg*2+ksh), 16 chunks of 128 floats: addr = chunk*128 + lane*4 + j
//  B chunk (ntg*2+ksh), 16 chunks of  64 floats: addr = chunk*64  + lane*2 + j
// Staging: warp w stages A chunks w and w+8, and B chunks w and w+8.
template<int ACT>
__device__ __forceinline__ void gemm_core(
    const float* __restrict__ A, const float* __restrict__ W,
    const float* __restrict__ bias, float* __restrict__ C,
    int M, int N, int K,
    const float* __restrict__ res, float* __restrict__ C2,
    float* As, float* Bs)
{
    const int tid = threadIdx.x;
    const int row0 = blockIdx.y*128, col0 = blockIdx.x*64;
    const int wid = tid>>5, lane = tid&31;
    const int wm = wid>>1, wn = wid&1;
    const int q = lane>>2, r = lane&3;

    float acc[2][4][4];
    #pragma unroll
    for(int i=0;i<2;i++)
      #pragma unroll
      for(int j=0;j<4;j++)
        #pragma unroll
        for(int c=0;c<4;c++) acc[i][j][c]=0.f;

    // ---- staging assignment ----
    const int c0  = wid;              // 0..7
    const int mt0 = c0>>1, ksh0 = c0&1;
    // A rows: chunk c0 -> rows mt0*16+q, +8 ; chunk c0+8 -> +64 rows
    const float* parow0 = A + (size_t)(row0 + mt0*16 + q)*K + ksh0*8 + r;
    const float* parow1 = parow0 + (size_t)8*K;
    const float* parow2 = parow0 + (size_t)64*K;
    const float* parow3 = parow2 + (size_t)8*K;
    // B rows: chunk c0 -> n = col0 + (c0>>1)*8 + q ; chunk c0+8 -> +32 cols
    const int bn0 = col0 + (c0>>1)*8 + q;
    const int bn1 = bn0 + 32;
    const bool vb0 = bn0 < N;
    const bool vb1 = bn1 < N;
    const float* pbrow0 = W + (size_t)(vb0 ? bn0 : 0)*K + ksh0*8 + r;
    const float* pbrow1 = W + (size_t)(vb1 ? bn1 : 0)*K + ksh0*8 + r;

    float* stA0 = As + c0*128     + lane*4;
    float* stA1 = As + (c0+8)*128 + lane*4;
    float* stB0 = Bs + c0*64      + lane*2;
    float* stB1 = Bs + (c0+8)*64  + lane*2;

    float ra[8], rbv[4];
    auto LD = [&](int t){
        int off = t*16;
        ra[0]=parow0[off];   ra[1]=parow1[off];
        ra[2]=parow0[off+4]; ra[3]=parow1[off+4];
        ra[4]=parow2[off];   ra[5]=parow3[off];
        ra[6]=parow2[off+4]; ra[7]=parow3[off+4];
        rbv[0] = vb0 ? pbrow0[off]   : 0.f;
        rbv[1] = vb0 ? pbrow0[off+4] : 0.f;
        rbv[2] = vb1 ? pbrow1[off]   : 0.f;
        rbv[3] = vb1 ? pbrow1[off+4] : 0.f;
    };
    auto ST = [&](int buf){
        *(float4*)(stA0 + buf*2048) = make_float4(ra[0],ra[1],ra[2],ra[3]);
        *(float4*)(stA1 + buf*2048) = make_float4(ra[4],ra[5],ra[6],ra[7]);
        *(float2*)(stB0 + buf*1024) = make_float2(rbv[0],rbv[1]);
        *(float2*)(stB1 + buf*1024) = make_float2(rbv[2],rbv[3]);
    };

    LD(0); ST(0);
    const int T = K>>4;
    for (int t=0; t<T; t++){
        __syncthreads();
        if (t+1 < T) LD(t+1);
        const float* as = As + (t&1)*2048;
        const float* bs = Bs + (t&1)*1024;
        #pragma unroll
        for (int ksh=0; ksh<2; ksh++){
            unsigned ah[2][4], al[2][4];
            #pragma unroll
            for (int mt=0; mt<2; mt++){
                int mtg = wm*2+mt;
                float4 v = *(const float4*)(as + (mtg*2+ksh)*128 + lane*4);
                float f[4]={v.x,v.y,v.z,v.w};
                #pragma unroll
                for (int j=0;j<4;j++){
                    unsigned h = f2tf32(f[j]);
                    ah[mt][j] = h;
                    al[mt][j] = __float_as_uint(f[j] - __uint_as_float(h));
                }
            }
            unsigned bh[4][2], bl[4][2];
            #pragma unroll
            for (int nt=0; nt<4; nt++){
                int ntg = wn*4+nt;
                float2 v = *(const float2*)(bs + (ntg*2+ksh)*64 + lane*2);
                float f[2]={v.x,v.y};
                #pragma unroll
                for (int j=0;j<2;j++){
                    unsigned h = f2tf32(f[j]);
                    bh[nt][j] = h;
                    bl[nt][j] = __float_as_uint(f[j] - __uint_as_float(h));
                }
            }
            #pragma unroll
            for (int mt=0; mt<2; mt++)
              #pragma unroll
              for (int nt=0; nt<4; nt++){
                  mma_tf32(acc[mt][nt], ah[mt], bh[nt]);   // hi*hi
                  mma_tf32(acc[mt][nt], al[mt], bh[nt]);   // lo*hi
                  mma_tf32(acc[mt][nt], ah[mt], bl[nt]);   // hi*lo
              }
        }
        if (t+1 < T) ST((t+1)&1);
    }

    // epilogue
    #pragma unroll
    for (int mt=0; mt<2; mt++){
        int Rbase = row0 + wm*32 + mt*16 + q;
        #pragma unroll
        for (int nt=0; nt<4; nt++){
            int Cbase = col0 + wn*32 + nt*8 + 2*r;
            #pragma unroll
            for (int cc=0; cc<4; cc++){
                int rr = Rbase + ((cc>=2)?8:0);
                int cl = Cbase + (cc&1);
                if (rr < M && cl < N){
                    float v = acc[mt][nt][cc] + (bias ? bias[cl] : 0.f);
                    if (ACT==1) v = gelu_exact(v);
                    size_t idx = (size_t)rr*N + cl;
                    if (C)  C[idx]  = v;
                    if (C2) C2[idx] = v + res[idx];
                }
            }
        }
    }
}

template<int ACT>
__global__ void __launch_bounds__(256) k_gemm(
    const float* __restrict__ A, const float* __restrict__ W,
    const float* __restrict__ bias, float* __restrict__ C,
    int M, int N, int K,
    const float* __restrict__ res, float* __restrict__ C2)
{
    __shared__ __align__(16) float As[4096];
    __shared__ __align__(16) float Bs[2048];
    gemm_core<ACT>(A, W, bias, C, M, N, K, res, C2, As, Bs);
}

// two independent no-bias GEMMs (LoRA t1 & g) in one launch via blockIdx.z
__global__ void __launch_bounds__(256) k_gemm_dual(
    const float* __restrict__ A0, const float* __restrict__ W0, int K0, float* __restrict__ C0,
    const float* __restrict__ A1, const float* __restrict__ W1, int K1, float* __restrict__ C1,
    int M, int N)
{
    __shared__ __align__(16) float As[4096];
    __shared__ __align__(16) float Bs[2048];
    if (blockIdx.z == 0)
        gemm_core<0>(A0, W0, nullptr, C0, M, N, K0, nullptr, nullptr, As, Bs);
    else
        gemm_core<0>(A1, W1, nullptr, C1, M, N, K1, nullptr, nullptr, As, Bs);
}

// ---------------- attention (per (batch, head) block), packed QKV input ----------
__global__ void k_attn(const float* __restrict__ qkv, float* __restrict__ o){
    int b = blockIdx.x / NHh, hh = blockIdx.x % NHh;
    int tid = threadIdx.x;
    __shared__ float qs[Sz][HDd], ks[Sz][HDd], vs[Sz][HDd];
    __shared__ float sc[Sz][32];
    for (int idx = tid; idx < Sz*HDd; idx += 256){
        int s = idx / HDd, dd = idx % HDd;
        size_t base = ((size_t)(b*Sz + s))*QKVN + hh*HDd + dd;
        qs[s][dd] = qkv[base];
        ks[s][dd] = qkv[base + 768];
        vs[s][dd] = qkv[base + 1536];
    }
    __syncthreads();
    for (int idx = tid; idx < Sz*Sz; idx += 256){
        int i = idx / Sz, j = idx % Sz;
        float s = 0.f;
        #pragma unroll
        for (int dd = 0; dd < HDd; dd++) s += qs[i][dd]*ks[j][dd];
        sc[i][j] = s * 0.125f;
    }
    __syncthreads();
    if (tid < Sz){
        float mx = -1e30f;
        for (int j = 0; j < Sz; j++) mx = fmaxf(mx, sc[tid][j]);
        float sm = 0.f;
        for (int j = 0; j < Sz; j++){ float e = expf(sc[tid][j]-mx); sc[tid][j] = e; sm += e; }
        float inv = 1.f/sm;
        for (int j = 0; j < Sz; j++) sc[tid][j] *= inv;
    }
    __syncthreads();
    for (int idx = tid; idx < Sz*HDd; idx += 256){
        int i = idx / HDd, dd = idx % HDd;
        float s = 0.f;
        for (int j = 0; j < Sz; j++) s += sc[i][j]*vs[j][dd];
        o[((size_t)(b*Sz + i))*Hs + hh*HDd + dd] = s;
    }
}

// ---------------- mask prep ----------------
__global__ void k_prep(const float* __restrict__ mask, float* __restrict__ maskf,
                       float* __restrict__ cnt){
    int d = threadIdx.x;
    if (d < Dd){
        float s = 0.f;
        for (int r = 0; r < Rr; r++){
            float f = (mask[r*Dd+d] > 0.f) ? 1.f : 0.f;
            maskf[r*Dd+d] = f; s += f;
        }
        cnt[d] = s;
    }
}

// ---------------- pooled ----------------
__global__ void k_pool(const float* __restrict__ att, const float* __restrict__ maskf,
                       const float* __restrict__ cnt, float* __restrict__ pooled){
    int d = blockIdx.x / Bz, b = blockIdx.x % Bz;
    int tid = threadIdx.x;
    __shared__ float msk[Rr];
    if (tid < Rr) msk[tid] = maskf[tid*Dd + d];
    __syncthreads();
    float inv = 1.f / fmaxf(cnt[d], 1.f);
    #pragma unroll
    for (int j = 0; j < 3; j++){
        int hh = tid + j*256;
        float s = 0.f;
        for (int r = 0; r < Rr; r++)
            if (msk[r] != 0.f) s += att[((size_t)(b*Sz) + 1 + r)*Hs + hh];
        pooled[((size_t)(d*Bz + b))*Hs + hh] = s*inv;
    }
}

// ---------------- per-(b,d) classifier -> active flag ----------------
__global__ void k_cls(const float* __restrict__ pooled, const float* __restrict__ cw1,
                      const float* __restrict__ cb1, const float* __restrict__ clg,
                      const float* __restrict__ clb, const float* __restrict__ cw2,
                      const float* __restrict__ cb2, const float* __restrict__ cnt,
                      float* __restrict__ actd){
    int d = blockIdx.x / Bz, b = blockIdx.x % Bz;
    int tid = threadIdx.x;   // 128 threads
    __shared__ float pol[Hs];
    __shared__ float h1[384];
    __shared__ float red[128], red2[128], stats[2];
    for (int i = tid; i < Hs; i += 128) pol[i] = pooled[((size_t)(d*Bz+b))*Hs + i];
    __syncthreads();
    for (int kx = tid; kx < 384; kx += 128){
        const float* wrow = cw1 + ((size_t)(d*384 + kx))*Hs;
        float s = cb1[d*384 + kx];
        for (int hh = 0; hh < Hs; hh++) s += pol[hh]*wrow[hh];
        h1[kx] = s;
    }
    __syncthreads();
    float l1 = 0.f, l2 = 0.f;
    for (int kx = tid; kx < 384; kx += 128){ float v = h1[kx]; l1 += v; l2 += v*v; }
    red[tid] = l1; red2[tid] = l2;
    __syncthreads();
    for (int st = 64; st > 0; st >>= 1){
        if (tid < st){ red[tid]+=red[tid+st]; red2[tid]+=red2[tid+st]; }
        __syncthreads();
    }
    if (tid == 0){
        float m = red[0]/384.f;
        stats[0] = m;
        stats[1] = rsqrtf(red2[0]/384.f - m*m + 1e-5f);
    }
    __syncthreads();
    float m = stats[0], inv = stats[1];
    float dot = 0.f;
    for (int kx = tid; kx < 384; kx += 128){
        float v = (h1[kx]-m)*inv*clg[d*384+kx] + clb[d*384+kx];
        v = gelu_exact(v);
        dot += v*cw2[d*384+kx];
    }
    __syncthreads();
    red[tid] = dot;
    __syncthreads();
    for (int st = 64; st > 0; st >>= 1){
        if (tid < st) red[tid] += red[tid+st];
        __syncthreads();
    }
    if (tid == 0){
        float pred = red[0] + cb2[d];
        actd[b*Dd + d] = (cnt[d] > 0.f && pred > 0.f) ? 1.f : 0.f;
    }
}

// ---------------- routing coefficients ----------------
__global__ void k_route(const float* __restrict__ actd, const float* __restrict__ maskf,
                        float* __restrict__ coef){
    int t = blockIdx.x*256 + threadIdx.x;
    if (t >= TOK) return;
    int b = t / Sz, s = t % Sz;
    float a[Dd]; float c = 1.f;
    #pragma unroll
    for (int d = 0; d < Dd; d++){
        float f = (s > 0) ? actd[b*Dd+d]*maskf[(s-1)*Dd+d] : 0.f;
        a[d] = f; c += f;
    }
    float w = 1.f / c;
    #pragma unroll
    for (int d = 0; d < Dd; d++) coef[t*Ee + d] = a[d]*w;
    coef[t*Ee + Dd] = w;
}

// ---------------- M_e = Ad_e @ Bu_e (8x8 per expert) ----------------
__global__ void k_loraM(const float* __restrict__ ad, const float* __restrict__ bu,
                        float* __restrict__ M){
    int e = blockIdx.x, idx = threadIdx.x;   // 64 threads
    int rp = idx / LRr, r = idx % LRr;
    const float* Ad = ad + ((size_t)e*LRr + rp)*Is;
    const float* Bu = bu + (size_t)e*Is*LRr + r;
    float s = 0.f;
    for (int i = 0; i < Is; i++) s += Ad[i]*Bu[(size_t)i*LRr];
    M[e*64 + idx] = s;
}

// ---------------- fused expert mix ----------------
__global__ void k_mix(const float* __restrict__ bout, const float* __restrict__ res1,
                      const float* __restrict__ t1, const float* __restrict__ g,
                      const float* __restrict__ M, const float* __restrict__ Bd,
                      const float* __restrict__ coef, float* __restrict__ hout){
    int t = blockIdx.x, tid = threadIdx.x;   // 256 threads, 3 h/thread
    __shared__ float gsh[LRr];
    __shared__ float red[256], red2[256], stats[2];
    float bo[3], r1[3], acc[3] = {0.f, 0.f, 0.f};
    #pragma unroll
    for (int j = 0; j < 3; j++){
        int hh = tid + j*256;
        bo[j] = bout[(size_t)t*Hs + hh];
        r1[j] = res1[(size_t)t*Hs + hh];
    }
    for (int e = 0; e < Ee; e++){
        float c = coef[t*Ee + e];
        if (c == 0.f) continue;
        __syncthreads();
        if (tid < LRr){
            float s = g[(size_t)t*(Ee*LRr) + e*LRr + tid];
            #pragma unroll
            for (int r = 0; r < LRr; r++)
                s += LORA_SCAL * t1[(size_t)t*(Ee*LRr) + e*LRr + r] * M[e*64 + tid*LRr + r];
            gsh[tid] = s;
        }
        __syncthreads();
        float o[3]; float l1 = 0.f, l2 = 0.f;
        #pragma unroll
        for (int j = 0; j < 3; j++){
            int hh = tid + j*256;
            const float* bdrow = Bd + ((size_t)e*Hs + hh)*LRr;
            float dn = 0.f;
            #pragma unroll
            for (int rp = 0; rp < LRr; rp++) dn += gsh[rp]*bdrow[rp];
            o[j] = bo[j] + LORA_SCAL*dn;
            l1 += o[j]; l2 += o[j]*o[j];
        }
        red[tid] = l1; red2[tid] = l2;
        __syncthreads();
        for (int st = 128; st > 0; st >>= 1){
            if (tid < st){ red[tid]+=red[tid+st]; red2[tid]+=red2[tid+st]; }
            __syncthreads();
        }
        if (tid == 0){
            float m = red[0]/768.f;
            stats[0] = m;
            stats[1] = rsqrtf(red2[0]/768.f - m*m + 1e-5f);
        }
        __syncthreads();
        float m = stats[0], inv = stats[1];
        #pragma unroll
        for (int j = 0; j < 3; j++) acc[j] += c*(o[j]-m)*inv;
    }
    #pragma unroll
    for (int j = 0; j < 3; j++)
        hout[(size_t)t*Hs + tid + j*256] = acc[j] + r1[j];
}

// ============================ host launch ============================
extern "C" void kernel_launch(void* const* d_in, const int* in_sizes, int n_in,
                              void* d_out, int out_size){
    const float* region = (const float*)d_in[0];
    const float* cls    = (const float*)d_in[1];
    const float* ln1g   = (const float*)d_in[2];
    const float* ln1b   = (const float*)d_in[3];
    const float* ln2g   = (const float*)d_in[4];
    const float* ln2b   = (const float*)d_in[5];
    const float* wq     = (const float*)d_in[6];
    const float* bq     = (const float*)d_in[7];
    const float* wk     = (const float*)d_in[8];
    const float* bk     = (const float*)d_in[9];
    const float* wv     = (const float*)d_in[10];
    const float* bv     = (const float*)d_in[11];
    const float* wo     = (const float*)d_in[12];
    const float* bo     = (const float*)d_in[13];
    const float* wi     = (const float*)d_in[14];
    const float* bi     = (const float*)d_in[15];
    const float* wof    = (const float*)d_in[16];
    const float* bof    = (const float*)d_in[17];
    const float* lnfg   = (const float*)d_in[18];
    const float* lnfb   = (const float*)d_in[19];
    const float* au     = (const float*)d_in[20];
    const float* bu     = (const float*)d_in[21];
    const float* ad     = (const float*)d_in[22];
    const float* bd     = (const float*)d_in[23];
    const float* cw1    = (const float*)d_in[24];
    const float* cb1    = (const float*)d_in[25];
    const float* clg    = (const float*)d_in[26];
    const float* clb    = (const float*)d_in[27];
    const float* cw2    = (const float*)d_in[28];
    const float* cb2    = (const float*)d_in[29];
    const float* maskI  = (const float*)d_in[30];

    float *ph, *pnx, *pqkv, *pattc, *patt, *pres1, *pnres, *phid, *pbout;
    float *pt1, *pg, *ppool, *pcoef, *pM, *pmaskf, *pcnt, *pactd, *pwqkv, *pbqkv;
    cudaGetSymbolAddress((void**)&ph,    d_h);
    cudaGetSymbolAddress((void**)&pnx,   d_nx);
    cudaGetSymbolAddress((void**)&pqkv,  d_qkvb);
    cudaGetSymbolAddress((void**)&pattc, d_attc);
    cudaGetSymbolAddress((void**)&patt,  d_att);
    cudaGetSymbolAddress((void**)&pres1, d_res1);
    cudaGetSymbolAddress((void**)&pnres, d_nres);
    cudaGetSymbolAddress((void**)&phid,  d_hid);
    cudaGetSymbolAddress((void**)&pbout, d_bout);
    cudaGetSymbolAddress((void**)&pt1,   d_t1);
    cudaGetSymbolAddress((void**)&pg,    d_g);
    cudaGetSymbolAddress((void**)&ppool, d_pooled);
    cudaGetSymbolAddress((void**)&pcoef, d_coef);
    cudaGetSymbolAddress((void**)&pM,    d_M);
    cudaGetSymbolAddress((void**)&pmaskf,d_maskf);
    cudaGetSymbolAddress((void**)&pcnt,  d_cnt);
    cudaGetSymbolAddress((void**)&pactd, d_actd);
    cudaGetSymbolAddress((void**)&pwqkv, d_wqkv);
    cudaGetSymbolAddress((void**)&pbqkv, d_bqkv);

    const int NEL = TOK*Hs;
    dim3 gqkv(QKVN/64, TOK/128);     // 36 x 30
    dim3 g768(Hs/64,   TOK/128);     // 12 x 30
    dim3 gup (Is/64,   TOK/128);     // 48 x 30
    dim3 glora(2, TOK/128, 2);       // 2 x 30 x 2

    k_build<<<(NEL+255)/256, 256>>>(region, cls, ph);
    k_prep<<<1, 32>>>(maskI, pmaskf, pcnt);
    {
        long long tot = (long long)12*QKVN*Hs;
        k_packqkv<<<(unsigned)((tot+255)/256), 256>>>(wq, wk, wv, pwqkv);
        k_packb<<<(12*QKVN+255)/256, 256>>>(bq, bk, bv, pbqkv);
    }

    int ei = 0;
    for (int i = 0; i < 12; i++){
        k_ln<<<TOK, 256>>>(ph, pnx, ln1g + i*Hs, ln1b + i*Hs, 1e-12f);
        // fused QKV projection
        k_gemm<0><<<gqkv, 256>>>(pnx, pwqkv + (size_t)i*QKVN*Hs, pbqkv + i*QKVN,
                                 pqkv, TOK, QKVN, Hs, nullptr, nullptr);
        k_attn<<<Bz*NHh, 256>>>(pqkv, pattc);
        // O-proj: att + fused residual (res1 = att + h)
        k_gemm<0><<<g768, 256>>>(pattc, wo + (size_t)i*Hs*Hs, bo + i*Hs,
                                 patt, TOK, Hs, Hs, ph, pres1);
        k_ln<<<TOK, 256>>>(pres1, pnres, ln2g + i*Hs, ln2b + i*Hs, 1e-12f);
        k_gemm<1><<<gup, 256>>>(pnres, wi + (size_t)i*Is*Hs, bi + i*Is,
                                phid, TOK, Is, Hs, nullptr, nullptr);

        if (i % 2 == 1){
            // down-proj with fused residual: h = base_out + res1 (skip storing bout)
            k_gemm<0><<<g768, 256>>>(phid, wof + (size_t)i*Hs*Is, bof + i*Hs,
                                     nullptr, TOK, Hs, Is, pres1, ph);
        } else {
            k_gemm<0><<<g768, 256>>>(phid, wof + (size_t)i*Hs*Is, bof + i*Hs,
                                     pbout, TOK, Hs, Is, nullptr, nullptr);
            // classifiers -> routing
            k_pool<<<Dd*Bz, 256>>>(patt, pmaskf, pcnt, ppool);
            k_cls<<<Dd*Bz, 128>>>(ppool,
                                  cw1 + (size_t)ei*Dd*384*Hs, cb1 + (size_t)ei*Dd*384,
                                  clg + (size_t)ei*Dd*384,    clb + (size_t)ei*Dd*384,
                                  cw2 + (size_t)ei*Dd*384,    cb2 + (size_t)ei*Dd,
                                  pcnt, pactd);
            k_route<<<(TOK+255)/256, 256>>>(pactd, pmaskf, pcoef);
            k_loraM<<<Ee, 64>>>(ad + (size_t)ei*Ee*LRr*Is, bu + (size_t)ei*Ee*Is*LRr, pM);
            // t1 = nres@Au^T  and  g = hid@Ad^T  in one launch
            k_gemm_dual<<<glora, 256>>>(pnres, au + (size_t)ei*Ee*LRr*Hs, Hs, pt1,
                                        phid, ad + (size_t)ei*Ee*LRr*Is, Is, pg,
                                        TOK, Ee*LRr);
            k_mix<<<TOK, 256>>>(pbout, pres1, pt1, pg, pM,
                                bd + (size_t)ei*Ee*Hs*LRr, pcoef, ph);
            ei++;
        }
    }
    k_ln<<<TOK, 256>>>(ph, (float*)d_out, lnfg, lnfb, 1e-12f);
}